// round 2
// baseline (speedup 1.0000x reference)
#include <cuda_runtime.h>
#include <cuda_bf16.h>
#include <math.h>

// ---------------------------------------------------------------------------
// DLRM forward, fp32 baseline.
//   bottom MLP: 13 -> 512 -> 256 -> 128 (relu)
//   embedding gather: 26 tables x 100000 x 128
//   interaction: 27x27 gram, tril(k=-1) = 351 + bottom(128) + pad(1) = 480
//   top MLP: 480 -> 1024 -> 1024 -> 512 -> 256 -> 1 (relu..., sigmoid)
// ---------------------------------------------------------------------------

#define BATCH      16384
#define EMB_DIM    128
#define TABLE_SIZE 100000
#define NUM_CAT    26
#define NUM_FEATS  27
#define TOP_IN     480

// Scratch (static device globals; no allocation allowed)
__device__ float g_h1[BATCH * 512];
__device__ float g_h2[BATCH * 256];
__device__ float g_bot[BATCH * 128];
__device__ float g_x [BATCH * TOP_IN];
__device__ float g_t1[BATCH * 1024];
__device__ float g_t2[BATCH * 1024];
__device__ float g_t3[BATCH * 512];
__device__ float g_t4[BATCH * 256];

// ---------------------------------------------------------------------------
// SGEMM: C[M,N] = relu(A[M,K] @ W[N,K]^T + bias[N])
// Tiles: BM=BN=128, BK=8. 256 threads, each computes 8x8 (two 4x4 quads).
// Requires: M % 128 == 0, N % 128 == 0. K arbitrary (guarded).
// ---------------------------------------------------------------------------
__global__ __launch_bounds__(256, 2)
void sgemm_bias_relu(const float* __restrict__ A,
                     const float* __restrict__ W,
                     const float* __restrict__ bias,
                     float* __restrict__ C,
                     int M, int N, int K) {
    __shared__ float As[8][132];   // pad 132 -> conflict-free STS/LDS
    __shared__ float Bs[8][132];

    const int tid = threadIdx.x;
    const int bm = blockIdx.y * 128;
    const int bn = blockIdx.x * 128;
    const int tx = tid & 15;        // 0..15  -> col quads
    const int ty = tid >> 4;        // 0..15  -> row quads
    const int lk = tid & 7;         // k within tile for loads
    const int lr = tid >> 3;        // 0..31

    float acc[8][8];
#pragma unroll
    for (int i = 0; i < 8; i++)
#pragma unroll
        for (int j = 0; j < 8; j++) acc[i][j] = 0.f;

    for (int k0 = 0; k0 < K; k0 += 8) {
        const int kk = k0 + lk;
        const bool kv = (kk < K);
#pragma unroll
        for (int p = 0; p < 4; p++) {
            const int row = lr + p * 32;
            As[lk][row] = kv ? A[(size_t)(bm + row) * K + kk] : 0.f;
            Bs[lk][row] = kv ? W[(size_t)(bn + row) * K + kk] : 0.f;
        }
        __syncthreads();

#pragma unroll
        for (int k = 0; k < 8; k++) {
            float4 a0 = *(const float4*)&As[k][ty * 4];
            float4 a1 = *(const float4*)&As[k][64 + ty * 4];
            float4 b0 = *(const float4*)&Bs[k][tx * 4];
            float4 b1 = *(const float4*)&Bs[k][64 + tx * 4];
            float a[8] = {a0.x, a0.y, a0.z, a0.w, a1.x, a1.y, a1.z, a1.w};
            float b[8] = {b0.x, b0.y, b0.z, b0.w, b1.x, b1.y, b1.z, b1.w};
#pragma unroll
            for (int i = 0; i < 8; i++)
#pragma unroll
                for (int j = 0; j < 8; j++)
                    acc[i][j] += a[i] * b[j];
        }
        __syncthreads();
    }

    // epilogue: bias + relu, float4 stores
    const int rbase[2] = {bm + ty * 4, bm + 64 + ty * 4};
    const int cbase[2] = {bn + tx * 4, bn + 64 + tx * 4};
#pragma unroll
    for (int jh = 0; jh < 2; jh++) {
        const int col = cbase[jh];
        float4 bv = *(const float4*)&bias[col];
#pragma unroll
        for (int ih = 0; ih < 2; ih++) {
#pragma unroll
            for (int i = 0; i < 4; i++) {
                const int row = rbase[ih] + i;
                float4 v;
                v.x = acc[ih * 4 + i][jh * 4 + 0] + bv.x;
                v.y = acc[ih * 4 + i][jh * 4 + 1] + bv.y;
                v.z = acc[ih * 4 + i][jh * 4 + 2] + bv.z;
                v.w = acc[ih * 4 + i][jh * 4 + 3] + bv.w;
                v.x = v.x > 0.f ? v.x : 0.f;
                v.y = v.y > 0.f ? v.y : 0.f;
                v.z = v.z > 0.f ? v.z : 0.f;
                v.w = v.w > 0.f ? v.w : 0.f;
                *(float4*)&C[(size_t)row * N + col] = v;
            }
        }
    }
}

// ---------------------------------------------------------------------------
// Interaction: per-sample gather 26 embeddings + bottom into smem, compute
// 351 tril dot products, emit x[b, 0:128]=bottom, x[b,128:479]=tril, x[479]=0.
// ---------------------------------------------------------------------------
__global__ __launch_bounds__(256)
void interact_kernel(const float* __restrict__ bottom,
                     const int* __restrict__ cat,     // [26, BATCH]
                     const float* __restrict__ emb,   // [26, TABLE_SIZE, 128]
                     float* __restrict__ x) {         // [BATCH, 480]
    __shared__ float feats[NUM_FEATS][132];
    const int b = blockIdx.x;
    const int tid = threadIdx.x;

    for (int idx = tid; idx < NUM_FEATS * 32; idx += 256) {
        const int r = idx >> 5;
        const int q = idx & 31;
        const float4* src;
        if (r == 0) {
            src = (const float4*)(bottom + (size_t)b * 128);
        } else {
            const int ci = cat[(size_t)(r - 1) * BATCH + b];
            src = (const float4*)(emb + ((size_t)(r - 1) * TABLE_SIZE + ci) * 128);
        }
        float4 v = src[q];
        feats[r][q * 4 + 0] = v.x;
        feats[r][q * 4 + 1] = v.y;
        feats[r][q * 4 + 2] = v.z;
        feats[r][q * 4 + 3] = v.w;
    }
    __syncthreads();

    float* xb = x + (size_t)b * TOP_IN;

    // bottom copy
    for (int i = tid; i < 32; i += 256) {
        *((float4*)xb + i) = *(const float4*)&feats[0][i * 4];
    }
    if (tid == 0) xb[TOP_IN - 1] = 0.f;

    // tril pairs (row-major over r=1..26, c=0..r-1)
    for (int p = tid; p < 351; p += 256) {
        int r = 1;
        while ((r + 1) * r / 2 <= p) r++;
        const int c = p - r * (r - 1) / 2;
        float s = 0.f;
#pragma unroll 8
        for (int k = 0; k < 128; k += 4) {
            float4 u = *(const float4*)&feats[r][k];
            float4 v = *(const float4*)&feats[c][k];
            s += u.x * v.x + u.y * v.y + u.z * v.z + u.w * v.w;
        }
        xb[128 + p] = s;
    }
}

// ---------------------------------------------------------------------------
// Final layer: out[b] = sigmoid(dot(t4[b,:256], w5) + b5). Warp per sample.
// ---------------------------------------------------------------------------
__global__ __launch_bounds__(256)
void final_layer(const float* __restrict__ A,    // [BATCH, 256]
                 const float* __restrict__ w5,   // [256]
                 const float* __restrict__ b5,   // [1]
                 float* __restrict__ out) {      // [BATCH]
    const int gwarp = (blockIdx.x * blockDim.x + threadIdx.x) >> 5;
    const int lane = threadIdx.x & 31;
    if (gwarp >= BATCH) return;
    const float4* a4 = (const float4*)(A + (size_t)gwarp * 256);
    const float4* w4 = (const float4*)w5;
    float s = 0.f;
#pragma unroll
    for (int i = lane; i < 64; i += 32) {
        float4 u = a4[i];
        float4 v = w4[i];
        s += u.x * v.x + u.y * v.y + u.z * v.z + u.w * v.w;
    }
#pragma unroll
    for (int o = 16; o; o >>= 1) s += __shfl_xor_sync(0xffffffffu, s, o);
    if (lane == 0) out[gwarp] = 1.f / (1.f + expf(-(s + b5[0])));
}

// ---------------------------------------------------------------------------
extern "C" void kernel_launch(void* const* d_in, const int* in_sizes, int n_in,
                              void* d_out, int out_size) {
    const float* num = (const float*)d_in[0];
    const int*   cat = (const int*)  d_in[1];
    const float* emb = (const float*)d_in[2];
    const float* bw1 = (const float*)d_in[3];
    const float* bb1 = (const float*)d_in[4];
    const float* bw2 = (const float*)d_in[5];
    const float* bb2 = (const float*)d_in[6];
    const float* bw3 = (const float*)d_in[7];
    const float* bb3 = (const float*)d_in[8];
    const float* tw1 = (const float*)d_in[9];
    const float* tb1 = (const float*)d_in[10];
    const float* tw2 = (const float*)d_in[11];
    const float* tb2 = (const float*)d_in[12];
    const float* tw3 = (const float*)d_in[13];
    const float* tb3 = (const float*)d_in[14];
    const float* tw4 = (const float*)d_in[15];
    const float* tb4 = (const float*)d_in[16];
    const float* tw5 = (const float*)d_in[17];
    const float* tb5 = (const float*)d_in[18];
    float* out = (float*)d_out;

    float *h1, *h2, *bot, *x, *t1, *t2, *t3, *t4;
    cudaGetSymbolAddress((void**)&h1,  g_h1);
    cudaGetSymbolAddress((void**)&h2,  g_h2);
    cudaGetSymbolAddress((void**)&bot, g_bot);
    cudaGetSymbolAddress((void**)&x,   g_x);
    cudaGetSymbolAddress((void**)&t1,  g_t1);
    cudaGetSymbolAddress((void**)&t2,  g_t2);
    cudaGetSymbolAddress((void**)&t3,  g_t3);
    cudaGetSymbolAddress((void**)&t4,  g_t4);

    const int MB = BATCH / 128;  // 128 row-tiles

    // bottom MLP
    sgemm_bias_relu<<<dim3(512 / 128, MB), 256>>>(num, bw1, bb1, h1, BATCH, 512, 13);
    sgemm_bias_relu<<<dim3(256 / 128, MB), 256>>>(h1, bw2, bb2, h2, BATCH, 256, 512);
    sgemm_bias_relu<<<dim3(128 / 128, MB), 256>>>(h2, bw3, bb3, bot, BATCH, 128, 256);

    // embedding gather + interaction
    interact_kernel<<<BATCH, 256>>>(bot, cat, emb, x);

    // top MLP
    sgemm_bias_relu<<<dim3(1024 / 128, MB), 256>>>(x,  tw1, tb1, t1, BATCH, 1024, TOP_IN);
    sgemm_bias_relu<<<dim3(1024 / 128, MB), 256>>>(t1, tw2, tb2, t2, BATCH, 1024, 1024);
    sgemm_bias_relu<<<dim3(512  / 128, MB), 256>>>(t2, tw3, tb3, t3, BATCH, 512, 1024);
    sgemm_bias_relu<<<dim3(256  / 128, MB), 256>>>(t3, tw4, tb4, t4, BATCH, 256, 512);

    // final dot + sigmoid
    final_layer<<<(BATCH * 32 + 255) / 256, 256>>>(t4, tw5, tb5, out);
}

// round 4
// speedup vs baseline: 1.3917x; 1.3917x over previous
#include <cuda_runtime.h>
#include <cuda_bf16.h>
#include <mma.h>
#include <math.h>
#include <stdint.h>

using namespace nvcuda;

// ===========================================================================
// DLRM forward. wmma TF32 (legacy HMMA, baseline PTX) GEMMs.
//   bottom: 13 -> 512 -> 256 -> 128, interaction, top: 480 -> 1024 -> 1024
//   -> 512 -> 256 -> 1 (sigmoid)
// ===========================================================================

#define BATCH      16384
#define EMB_DIM    128
#define TABLE_SIZE 100000
#define NUM_CAT    26
#define NUM_FEATS  27
#define TOP_IN     480

// ------------------------- scratch (device globals) ------------------------
__device__ float g_h1[BATCH * 512];
__device__ float g_h2[BATCH * 256];
__device__ float g_bot[BATCH * 128];
__device__ float g_x [BATCH * TOP_IN];
__device__ float g_t1[BATCH * 1024];
__device__ float g_t2[BATCH * 1024];
__device__ float g_t3[BATCH * 512];
__device__ float g_t4[BATCH * 256];
// tf32-rounded weight copies
__device__ float g_bw2r[256 * 512];
__device__ float g_bw3r[128 * 256];
__device__ float g_tw1r[1024 * TOP_IN];
__device__ float g_tw2r[1024 * 1024];
__device__ float g_tw3r[512 * 1024];
__device__ float g_tw4r[256 * 512];

// ------------------------------ helpers ------------------------------------
__device__ __forceinline__ uint32_t smem_u32(const void* p) {
    return (uint32_t)__cvta_generic_to_shared(p);
}
__device__ __forceinline__ float to_tf32(float x) {
    float y;
    asm("cvt.rna.tf32.f32 %0, %1;" : "=f"(y) : "f"(x));
    return y;
}
#define CP_ASYNC16(dst, src) \
    asm volatile("cp.async.cg.shared.global [%0], [%1], 16;" :: "r"(dst), "l"(src))
__device__ __forceinline__ void cp_commit() { asm volatile("cp.async.commit_group;"); }
__device__ __forceinline__ void cp_wait1() { asm volatile("cp.async.wait_group 1;"); }
__device__ __forceinline__ void cp_wait0() { asm volatile("cp.async.wait_group 0;"); }

// ===========================================================================
// wmma TF32 GEMM:  C[M,N] = relu(A[M,K] @ W[N,K]^T + bias)
// CTA 128x128, BK=32, double-buffered cp.async. 8 warps, each 64x32.
// Requires M%128==0, N%128==0, K%32==0. A, W pre-rounded to tf32.
// smem per stage: A[128][36] + B[128][36] floats = 36,864 B; 2 stages.
// Epilogue stages C (128x132 floats) over the pipeline buffers.
// ===========================================================================
#define LDM 36
#define STAGE_BYTES (2 * 128 * LDM * 4)   // A+B one stage = 36864

__global__ __launch_bounds__(256, 2)
void wmma_gemm(const float* __restrict__ A, const float* __restrict__ W,
               const float* __restrict__ bias, float* __restrict__ C,
               int N, int K, int round_out) {
    extern __shared__ float smem[];
    const int tid = threadIdx.x;
    const int warp = tid >> 5;
    const int bm = blockIdx.y * 128;
    const int bn = blockIdx.x * 128;
    const int wm = warp >> 2;        // 0..1 -> 64-row half
    const int wn = warp & 3;         // 0..3 -> 32-col quarter
    const uint32_t sb = smem_u32(smem);

    // stage s: A at smem + s*STAGE, B at smem + s*STAGE + 128*LDM floats
    auto As = [&](int s) -> float* { return smem + (size_t)s * (2 * 128 * LDM); };
    auto Bs = [&](int s) -> float* { return smem + (size_t)s * (2 * 128 * LDM) + 128 * LDM; };

    wmma::fragment<wmma::accumulator, 16, 16, 8, float> cf[4][2];
#pragma unroll
    for (int i = 0; i < 4; i++)
#pragma unroll
        for (int j = 0; j < 2; j++) wmma::fill_fragment(cf[i][j], 0.0f);

    const int T = K / 32;

    // loader: 128 rows x 8 float4 per tile; 256 threads -> 4 chunks each tile
    auto load_stage = [&](int t) {
        const int s = t & 1;
        const int k0 = t * 32;
        const uint32_t abase = sb + (uint32_t)s * STAGE_BYTES;
        const uint32_t bbase = abase + 128u * LDM * 4u;
#pragma unroll
        for (int i = 0; i < 4; i++) {
            int idx = tid + i * 256;
            int r = idx >> 3, c = idx & 7;
            CP_ASYNC16(abase + (uint32_t)(r * LDM + c * 4) * 4u,
                       A + (size_t)(bm + r) * K + k0 + c * 4);
        }
#pragma unroll
        for (int i = 0; i < 4; i++) {
            int idx = tid + i * 256;
            int r = idx >> 3, c = idx & 7;
            CP_ASYNC16(bbase + (uint32_t)(r * LDM + c * 4) * 4u,
                       W + (size_t)(bn + r) * K + k0 + c * 4);
        }
        cp_commit();
    };

    load_stage(0);
    for (int t = 0; t < T; t++) {
        if (t + 1 < T) { load_stage(t + 1); cp_wait1(); }
        else           { cp_wait0(); }
        __syncthreads();

        const float* a = As(t & 1);
        const float* b = Bs(t & 1);
#pragma unroll
        for (int kk = 0; kk < 32; kk += 8) {
            wmma::fragment<wmma::matrix_a, 16, 16, 8, wmma::precision::tf32, wmma::row_major> af[4];
            wmma::fragment<wmma::matrix_b, 16, 16, 8, wmma::precision::tf32, wmma::col_major> bf[2];
#pragma unroll
            for (int i = 0; i < 4; i++)
                wmma::load_matrix_sync(af[i], a + (wm * 64 + i * 16) * LDM + kk, LDM);
#pragma unroll
            for (int j = 0; j < 2; j++)
                wmma::load_matrix_sync(bf[j], b + (wn * 32 + j * 16) * LDM + kk, LDM);
#pragma unroll
            for (int i = 0; i < 4; i++)
#pragma unroll
                for (int j = 0; j < 2; j++)
                    wmma::mma_sync(cf[i][j], af[i], bf[j], cf[i][j]);
        }
        __syncthreads();
    }

    // ---------------- epilogue: fragments -> smem -> gmem ------------------
    float* cs = smem;   // [128][132]
#pragma unroll
    for (int i = 0; i < 4; i++)
#pragma unroll
        for (int j = 0; j < 2; j++)
            wmma::store_matrix_sync(cs + (size_t)(wm * 64 + i * 16) * 132 + wn * 32 + j * 16,
                                    cf[i][j], 132, wmma::mem_row_major);
    __syncthreads();

    {
        const int row = tid >> 1, h = tid & 1;           // 2 threads/row, 64 cols each
        const float* src = cs + (size_t)row * 132 + h * 64;
        float* dst = C + (size_t)(bm + row) * N + bn + h * 64;
        const float* bsrc = bias + bn + h * 64;
#pragma unroll
        for (int q = 0; q < 16; q++) {
            float4 v  = *(const float4*)(src + q * 4);
            float4 bv = *(const float4*)(bsrc + q * 4);
            v.x += bv.x; v.y += bv.y; v.z += bv.z; v.w += bv.w;
            v.x = v.x > 0.f ? v.x : 0.f;
            v.y = v.y > 0.f ? v.y : 0.f;
            v.z = v.z > 0.f ? v.z : 0.f;
            v.w = v.w > 0.f ? v.w : 0.f;
            if (round_out) {
                v.x = to_tf32(v.x); v.y = to_tf32(v.y);
                v.z = to_tf32(v.z); v.w = to_tf32(v.w);
            }
            *(float4*)(dst + q * 4) = v;
        }
    }
}

// ===========================================================================
// fp32 SGEMM for the K=13 bottom layer 1.
// ===========================================================================
__global__ __launch_bounds__(256, 2)
void sgemm_bias_relu(const float* __restrict__ A, const float* __restrict__ W,
                     const float* __restrict__ bias, float* __restrict__ C,
                     int M, int N, int K, int round_out) {
    __shared__ float As[8][132];
    __shared__ float Bs[8][132];
    const int tid = threadIdx.x;
    const int bm = blockIdx.y * 128, bn = blockIdx.x * 128;
    const int tx = tid & 15, ty = tid >> 4;
    const int lk = tid & 7, lr = tid >> 3;

    float acc[8][8];
#pragma unroll
    for (int i = 0; i < 8; i++)
#pragma unroll
        for (int j = 0; j < 8; j++) acc[i][j] = 0.f;

    for (int k0 = 0; k0 < K; k0 += 8) {
        const int kk = k0 + lk;
        const bool kv = (kk < K);
#pragma unroll
        for (int p = 0; p < 4; p++) {
            const int row = lr + p * 32;
            As[lk][row] = kv ? A[(size_t)(bm + row) * K + kk] : 0.f;
            Bs[lk][row] = kv ? W[(size_t)(bn + row) * K + kk] : 0.f;
        }
        __syncthreads();
#pragma unroll
        for (int k = 0; k < 8; k++) {
            float4 a0 = *(const float4*)&As[k][ty * 4];
            float4 a1 = *(const float4*)&As[k][64 + ty * 4];
            float4 b0 = *(const float4*)&Bs[k][tx * 4];
            float4 b1 = *(const float4*)&Bs[k][64 + tx * 4];
            float a[8] = {a0.x, a0.y, a0.z, a0.w, a1.x, a1.y, a1.z, a1.w};
            float b[8] = {b0.x, b0.y, b0.z, b0.w, b1.x, b1.y, b1.z, b1.w};
#pragma unroll
            for (int i = 0; i < 8; i++)
#pragma unroll
                for (int j = 0; j < 8; j++)
                    acc[i][j] += a[i] * b[j];
        }
        __syncthreads();
    }
    const int rbase[2] = {bm + ty * 4, bm + 64 + ty * 4};
    const int cbase[2] = {bn + tx * 4, bn + 64 + tx * 4};
#pragma unroll
    for (int jh = 0; jh < 2; jh++) {
        const int col = cbase[jh];
        float4 bv = *(const float4*)&bias[col];
#pragma unroll
        for (int ih = 0; ih < 2; ih++) {
#pragma unroll
            for (int i = 0; i < 4; i++) {
                const int row = rbase[ih] + i;
                float4 v;
                v.x = acc[ih * 4 + i][jh * 4 + 0] + bv.x;
                v.y = acc[ih * 4 + i][jh * 4 + 1] + bv.y;
                v.z = acc[ih * 4 + i][jh * 4 + 2] + bv.z;
                v.w = acc[ih * 4 + i][jh * 4 + 3] + bv.w;
                v.x = v.x > 0.f ? v.x : 0.f;
                v.y = v.y > 0.f ? v.y : 0.f;
                v.z = v.z > 0.f ? v.z : 0.f;
                v.w = v.w > 0.f ? v.w : 0.f;
                if (round_out) {
                    v.x = to_tf32(v.x); v.y = to_tf32(v.y);
                    v.z = to_tf32(v.z); v.w = to_tf32(v.w);
                }
                *(float4*)&C[(size_t)row * N + col] = v;
            }
        }
    }
}

// ===========================================================================
// Interaction: 3 samples/CTA, 4x4 register-blocked gram, tf32-rounded output.
// ===========================================================================
__global__ __launch_bounds__(96)
void interact2(const float* __restrict__ bottom, const int* __restrict__ cat,
               const float* __restrict__ emb, float* __restrict__ x) {
    __shared__ float feats[3][NUM_FEATS][132];
    const int tid = threadIdx.x;
    const int b0 = blockIdx.x * 3;

    for (int idx = tid; idx < 3 * NUM_FEATS * 32; idx += 96) {
        const int s = idx / (NUM_FEATS * 32);
        const int rem = idx % (NUM_FEATS * 32);
        const int r = rem >> 5, q = rem & 31;
        const int b = b0 + s;
        if (b >= BATCH) continue;
        const float4* src;
        if (r == 0) {
            src = (const float4*)(bottom + (size_t)b * 128);
        } else {
            const int ci = cat[(size_t)(r - 1) * BATCH + b];
            src = (const float4*)(emb + ((size_t)(r - 1) * TABLE_SIZE + ci) * 128);
        }
        float4 v = src[q];
        feats[s][r][q * 4 + 0] = v.x;
        feats[s][r][q * 4 + 1] = v.y;
        feats[s][r][q * 4 + 2] = v.z;
        feats[s][r][q * 4 + 3] = v.w;
    }
    __syncthreads();

    {   // bottom copy + pad
        const int s = tid >> 5, q = tid & 31;
        const int b = b0 + s;
        if (b < BATCH) {
            float* xb = x + (size_t)b * TOP_IN;
            float4 v = *(const float4*)&feats[s][0][q * 4];
            v.x = to_tf32(v.x); v.y = to_tf32(v.y);
            v.z = to_tf32(v.z); v.w = to_tf32(v.w);
            *(float4*)(xb + q * 4) = v;
            if (q == 0) xb[TOP_IN - 1] = 0.f;
        }
    }

    if (tid < 84) {
        const int s = tid / 28, blk = tid % 28;
        const int b = b0 + s;
        if (b < BATCH) {
            int R = 0;
            while ((R + 1) * (R + 2) / 2 <= blk) R++;
            const int Cc = blk - R * (R + 1) / 2;
            const int r0 = 4 * R, c0 = 4 * Cc;
            const float (*fs)[132] = feats[s];

            float acc[4][4];
#pragma unroll
            for (int i = 0; i < 4; i++)
#pragma unroll
                for (int j = 0; j < 4; j++) acc[i][j] = 0.f;

            const int ra[4] = {r0 < 27 ? r0 : 0, r0 + 1 < 27 ? r0 + 1 : 0,
                               r0 + 2 < 27 ? r0 + 2 : 0, r0 + 3 < 27 ? r0 + 3 : 0};
            const int ca[4] = {c0 < 27 ? c0 : 0, c0 + 1 < 27 ? c0 + 1 : 0,
                               c0 + 2 < 27 ? c0 + 2 : 0, c0 + 3 < 27 ? c0 + 3 : 0};

            for (int k = 0; k < 128; k += 4) {
                float4 av[4], bv[4];
#pragma unroll
                for (int i = 0; i < 4; i++) av[i] = *(const float4*)&fs[ra[i]][k];
#pragma unroll
                for (int j = 0; j < 4; j++) bv[j] = *(const float4*)&fs[ca[j]][k];
#pragma unroll
                for (int i = 0; i < 4; i++)
#pragma unroll
                    for (int j = 0; j < 4; j++)
                        acc[i][j] += av[i].x * bv[j].x + av[i].y * bv[j].y +
                                     av[i].z * bv[j].z + av[i].w * bv[j].w;
            }
            float* xb = x + (size_t)b * TOP_IN;
#pragma unroll
            for (int i = 0; i < 4; i++)
#pragma unroll
                for (int j = 0; j < 4; j++) {
                    const int r = r0 + i, c = c0 + j;
                    if (r < NUM_FEATS && c < r)
                        xb[128 + r * (r - 1) / 2 + c] = to_tf32(acc[i][j]);
                }
        }
    }
}

// ===========================================================================
__global__ void round_tf32(const float* __restrict__ src, float* __restrict__ dst, int n) {
    int i = blockIdx.x * blockDim.x + threadIdx.x;
    if (i < n) dst[i] = to_tf32(src[i]);
}

__global__ __launch_bounds__(256)
void final_layer(const float* __restrict__ A, const float* __restrict__ w5,
                 const float* __restrict__ b5, float* __restrict__ out) {
    const int gwarp = (blockIdx.x * blockDim.x + threadIdx.x) >> 5;
    const int lane = threadIdx.x & 31;
    if (gwarp >= BATCH) return;
    const float4* a4 = (const float4*)(A + (size_t)gwarp * 256);
    const float4* w4 = (const float4*)w5;
    float s = 0.f;
#pragma unroll
    for (int i = lane; i < 64; i += 32) {
        float4 u = a4[i];
        float4 v = w4[i];
        s += u.x * v.x + u.y * v.y + u.z * v.z + u.w * v.w;
    }
#pragma unroll
    for (int o = 16; o; o >>= 1) s += __shfl_xor_sync(0xffffffffu, s, o);
    if (lane == 0) out[gwarp] = 1.f / (1.f + expf(-(s + b5[0])));
}

// ===========================================================================
extern "C" void kernel_launch(void* const* d_in, const int* in_sizes, int n_in,
                              void* d_out, int out_size) {
    const float* num = (const float*)d_in[0];
    const int*   cat = (const int*)  d_in[1];
    const float* emb = (const float*)d_in[2];
    const float* bw1 = (const float*)d_in[3];
    const float* bb1 = (const float*)d_in[4];
    const float* bw2 = (const float*)d_in[5];
    const float* bb2 = (const float*)d_in[6];
    const float* bw3 = (const float*)d_in[7];
    const float* bb3 = (const float*)d_in[8];
    const float* tw1 = (const float*)d_in[9];
    const float* tb1 = (const float*)d_in[10];
    const float* tw2 = (const float*)d_in[11];
    const float* tb2 = (const float*)d_in[12];
    const float* tw3 = (const float*)d_in[13];
    const float* tb3 = (const float*)d_in[14];
    const float* tw4 = (const float*)d_in[15];
    const float* tb4 = (const float*)d_in[16];
    const float* tw5 = (const float*)d_in[17];
    const float* tb5 = (const float*)d_in[18];
    float* out = (float*)d_out;

    float *h1, *h2, *bot, *x, *t1, *t2, *t3, *t4;
    float *bw2r, *bw3r, *tw1r, *tw2r, *tw3r, *tw4r;
    cudaGetSymbolAddress((void**)&h1,  g_h1);
    cudaGetSymbolAddress((void**)&h2,  g_h2);
    cudaGetSymbolAddress((void**)&bot, g_bot);
    cudaGetSymbolAddress((void**)&x,   g_x);
    cudaGetSymbolAddress((void**)&t1,  g_t1);
    cudaGetSymbolAddress((void**)&t2,  g_t2);
    cudaGetSymbolAddress((void**)&t3,  g_t3);
    cudaGetSymbolAddress((void**)&t4,  g_t4);
    cudaGetSymbolAddress((void**)&bw2r, g_bw2r);
    cudaGetSymbolAddress((void**)&bw3r, g_bw3r);
    cudaGetSymbolAddress((void**)&tw1r, g_tw1r);
    cudaGetSymbolAddress((void**)&tw2r, g_tw2r);
    cudaGetSymbolAddress((void**)&tw3r, g_tw3r);
    cudaGetSymbolAddress((void**)&tw4r, g_tw4r);

    const int SMEM = 2 * STAGE_BYTES;   // 73728
    cudaFuncSetAttribute(wmma_gemm, cudaFuncAttributeMaxDynamicSharedMemorySize, SMEM);

    // round weights to tf32 (RN) into scratch
    round_tf32<<<(256 * 512  + 255) / 256, 256>>>(bw2, bw2r, 256 * 512);
    round_tf32<<<(128 * 256  + 255) / 256, 256>>>(bw3, bw3r, 128 * 256);
    round_tf32<<<(1024 * TOP_IN + 255) / 256, 256>>>(tw1, tw1r, 1024 * TOP_IN);
    round_tf32<<<(1024 * 1024 + 255) / 256, 256>>>(tw2, tw2r, 1024 * 1024);
    round_tf32<<<(512 * 1024 + 255) / 256, 256>>>(tw3, tw3r, 512 * 1024);
    round_tf32<<<(256 * 512  + 255) / 256, 256>>>(tw4, tw4r, 256 * 512);

    const int MB = BATCH / 128;  // 128

    // bottom MLP
    sgemm_bias_relu<<<dim3(4, MB), 256>>>(num, bw1, bb1, h1, BATCH, 512, 13, 1);
    wmma_gemm<<<dim3(2, MB), 256, SMEM>>>(h1, bw2r, bb2, h2, 256, 512, 1);
    wmma_gemm<<<dim3(1, MB), 256, SMEM>>>(h2, bw3r, bb3, bot, 128, 256, 0);

    // embedding gather + interaction (tf32-rounds its outputs)
    interact2<<<(BATCH + 2) / 3, 96>>>(bot, cat, emb, x);

    // top MLP
    wmma_gemm<<<dim3(8, MB), 256, SMEM>>>(x,  tw1r, tb1, t1, 1024, TOP_IN, 1);
    wmma_gemm<<<dim3(8, MB), 256, SMEM>>>(t1, tw2r, tb2, t2, 1024, 1024, 1);
    wmma_gemm<<<dim3(4, MB), 256, SMEM>>>(t2, tw3r, tb3, t3, 512, 1024, 1);
    wmma_gemm<<<dim3(2, MB), 256, SMEM>>>(t3, tw4r, tb4, t4, 256, 512, 0);

    // final dot + sigmoid
    final_layer<<<(BATCH * 32 + 255) / 256, 256>>>(t4, tw5, tb5, out);
}

// round 5
// speedup vs baseline: 3.2227x; 2.3158x over previous
#include <cuda_runtime.h>
#include <cuda_bf16.h>
#include <mma.h>
#include <math.h>
#include <stdint.h>

using namespace nvcuda;

// ===========================================================================
// DLRM forward. bf16 wmma (m16n16k16 HMMA) GEMMs, fp32 accumulate.
// Activations/weights bf16; interaction gram in fp32 from fp32 embeddings.
// ===========================================================================

#define BATCH      16384
#define EMB_DIM    128
#define TABLE_SIZE 100000
#define NUM_CAT    26
#define NUM_FEATS  27
#define TOP_IN     480
#define TOP_IN_P   512          // padded K for top layer 1

// ------------------------- scratch (device globals) ------------------------
__device__ __nv_bfloat16 g_h1[BATCH * 512];
__device__ __nv_bfloat16 g_h2[BATCH * 256];
__device__ __nv_bfloat16 g_bot[BATCH * 128];
__device__ __nv_bfloat16 g_x [BATCH * TOP_IN_P];
__device__ __nv_bfloat16 g_t1[BATCH * 1024];
__device__ __nv_bfloat16 g_t2[BATCH * 1024];
__device__ __nv_bfloat16 g_t3[BATCH * 512];
__device__ __nv_bfloat16 g_t4[BATCH * 256];
// bf16-rounded weights
__device__ __nv_bfloat16 g_bw2r[256 * 512];
__device__ __nv_bfloat16 g_bw3r[128 * 256];
__device__ __nv_bfloat16 g_tw1r[1024 * TOP_IN_P];   // zero-padded K
__device__ __nv_bfloat16 g_tw2r[1024 * 1024];
__device__ __nv_bfloat16 g_tw3r[512 * 1024];
__device__ __nv_bfloat16 g_tw4r[256 * 512];

// ------------------------------ helpers ------------------------------------
__device__ __forceinline__ uint32_t smem_u32(const void* p) {
    return (uint32_t)__cvta_generic_to_shared(p);
}
#define CP_ASYNC16(dst, src) \
    asm volatile("cp.async.cg.shared.global [%0], [%1], 16;" :: "r"(dst), "l"(src))
__device__ __forceinline__ void cp_commit() { asm volatile("cp.async.commit_group;"); }
__device__ __forceinline__ void cp_wait1() { asm volatile("cp.async.wait_group 1;"); }
__device__ __forceinline__ void cp_wait0() { asm volatile("cp.async.wait_group 0;"); }

// ===========================================================================
// bf16 wmma GEMM:  C[M,N] = relu(A[M,K] @ W[N,K]^T + bias), C in bf16
// CTA 128x128, BK=64, double-buffered cp.async. 8 warps, each 64x32.
// Requires M%128==0, N%128==0, K%64==0.
// smem stage: (128+128) rows x 144B = 36864 B; 2 stages = 73728 B.
// ===========================================================================
#define LDM 72                              // bf16 elements; 144 B row stride
#define STAGE_BYTES (2 * 128 * LDM * 2)     // 36864

__global__ __launch_bounds__(256, 2)
void bf16_gemm(const __nv_bfloat16* __restrict__ A,
               const __nv_bfloat16* __restrict__ W,
               const float* __restrict__ bias,
               __nv_bfloat16* __restrict__ C,
               int N, int K) {
    extern __shared__ __nv_bfloat16 smem[];
    const int tid = threadIdx.x;
    const int warp = tid >> 5;
    const int bm = blockIdx.y * 128;
    const int bn = blockIdx.x * 128;
    const int wm = warp >> 2;        // 0..1 -> 64-row half
    const int wn = warp & 3;         // 0..3 -> 32-col quarter
    const uint32_t sb = smem_u32(smem);

    wmma::fragment<wmma::accumulator, 16, 16, 16, float> cf[4][2];
#pragma unroll
    for (int i = 0; i < 4; i++)
#pragma unroll
        for (int j = 0; j < 2; j++) wmma::fill_fragment(cf[i][j], 0.0f);

    const int T = K / 64;

    // loader: per matrix 128 rows x 8 chunks(16B) = 1024; 256 thr -> 4 each
    auto load_stage = [&](int t) {
        const int s = t & 1;
        const int k0 = t * 64;
        const uint32_t abase = sb + (uint32_t)s * STAGE_BYTES;
        const uint32_t bbase = abase + 128u * LDM * 2u;
#pragma unroll
        for (int i = 0; i < 4; i++) {
            int idx = tid + i * 256;
            int r = idx >> 3, c = idx & 7;
            CP_ASYNC16(abase + (uint32_t)(r * LDM + c * 8) * 2u,
                       A + (size_t)(bm + r) * K + k0 + c * 8);
        }
#pragma unroll
        for (int i = 0; i < 4; i++) {
            int idx = tid + i * 256;
            int r = idx >> 3, c = idx & 7;
            CP_ASYNC16(bbase + (uint32_t)(r * LDM + c * 8) * 2u,
                       W + (size_t)(bn + r) * K + k0 + c * 8);
        }
        cp_commit();
    };

    load_stage(0);
    for (int t = 0; t < T; t++) {
        if (t + 1 < T) { load_stage(t + 1); cp_wait1(); }
        else           { cp_wait0(); }
        __syncthreads();

        const __nv_bfloat16* a = smem + (size_t)(t & 1) * (2 * 128 * LDM);
        const __nv_bfloat16* b = a + 128 * LDM;
#pragma unroll
        for (int kk = 0; kk < 64; kk += 16) {
            wmma::fragment<wmma::matrix_a, 16, 16, 16, __nv_bfloat16, wmma::row_major> af[4];
            wmma::fragment<wmma::matrix_b, 16, 16, 16, __nv_bfloat16, wmma::col_major> bf[2];
#pragma unroll
            for (int i = 0; i < 4; i++)
                wmma::load_matrix_sync(af[i], a + (wm * 64 + i * 16) * LDM + kk, LDM);
#pragma unroll
            for (int j = 0; j < 2; j++)
                wmma::load_matrix_sync(bf[j], b + (wn * 32 + j * 16) * LDM + kk, LDM);
#pragma unroll
            for (int i = 0; i < 4; i++)
#pragma unroll
                for (int j = 0; j < 2; j++)
                    wmma::mma_sync(cf[i][j], af[i], bf[j], cf[i][j]);
        }
        __syncthreads();
    }

    // ---------------- epilogue: fragments -> smem(fp32) -> bf16 gmem -------
    float* cs = (float*)smem;   // [128][132] fp32 = 67584 B < 73728
#pragma unroll
    for (int i = 0; i < 4; i++)
#pragma unroll
        for (int j = 0; j < 2; j++)
            wmma::store_matrix_sync(cs + (size_t)(wm * 64 + i * 16) * 132 + wn * 32 + j * 16,
                                    cf[i][j], 132, wmma::mem_row_major);
    __syncthreads();

    {
        const int row = tid >> 1, h = tid & 1;       // 2 threads/row, 64 cols each
        const float* src = cs + (size_t)row * 132 + h * 64;
        __nv_bfloat16* dst = C + (size_t)(bm + row) * N + bn + h * 64;
        const float* bsrc = bias + bn + h * 64;
#pragma unroll
        for (int q = 0; q < 8; q++) {               // 8 cols per iter -> 16B store
            float4 v0 = *(const float4*)(src + q * 8);
            float4 v1 = *(const float4*)(src + q * 8 + 4);
            float4 b0 = *(const float4*)(bsrc + q * 8);
            float4 b1 = *(const float4*)(bsrc + q * 8 + 4);
            v0.x += b0.x; v0.y += b0.y; v0.z += b0.z; v0.w += b0.w;
            v1.x += b1.x; v1.y += b1.y; v1.z += b1.z; v1.w += b1.w;
            v0.x = v0.x > 0.f ? v0.x : 0.f;
            v0.y = v0.y > 0.f ? v0.y : 0.f;
            v0.z = v0.z > 0.f ? v0.z : 0.f;
            v0.w = v0.w > 0.f ? v0.w : 0.f;
            v1.x = v1.x > 0.f ? v1.x : 0.f;
            v1.y = v1.y > 0.f ? v1.y : 0.f;
            v1.z = v1.z > 0.f ? v1.z : 0.f;
            v1.w = v1.w > 0.f ? v1.w : 0.f;
            __nv_bfloat162 p0 = __floats2bfloat162_rn(v0.x, v0.y);
            __nv_bfloat162 p1 = __floats2bfloat162_rn(v0.z, v0.w);
            __nv_bfloat162 p2 = __floats2bfloat162_rn(v1.x, v1.y);
            __nv_bfloat162 p3 = __floats2bfloat162_rn(v1.z, v1.w);
            uint4 pk;
            pk.x = *(uint32_t*)&p0; pk.y = *(uint32_t*)&p1;
            pk.z = *(uint32_t*)&p2; pk.w = *(uint32_t*)&p3;
            *(uint4*)(dst + q * 8) = pk;
        }
    }
}

// ===========================================================================
// fp32 SGEMM for the K=13 bottom layer 1 -> bf16 out.
// ===========================================================================
__global__ __launch_bounds__(256, 2)
void sgemm_l1(const float* __restrict__ A, const float* __restrict__ W,
              const float* __restrict__ bias, __nv_bfloat16* __restrict__ C,
              int N, int K) {
    __shared__ float As[8][132];
    __shared__ float Bs[8][132];
    const int tid = threadIdx.x;
    const int bm = blockIdx.y * 128, bn = blockIdx.x * 128;
    const int tx = tid & 15, ty = tid >> 4;
    const int lk = tid & 7, lr = tid >> 3;

    float acc[8][8];
#pragma unroll
    for (int i = 0; i < 8; i++)
#pragma unroll
        for (int j = 0; j < 8; j++) acc[i][j] = 0.f;

    for (int k0 = 0; k0 < K; k0 += 8) {
        const int kk = k0 + lk;
        const bool kv = (kk < K);
#pragma unroll
        for (int p = 0; p < 4; p++) {
            const int row = lr + p * 32;
            As[lk][row] = kv ? A[(size_t)(bm + row) * K + kk] : 0.f;
            Bs[lk][row] = kv ? W[(size_t)(bn + row) * K + kk] : 0.f;
        }
        __syncthreads();
#pragma unroll
        for (int k = 0; k < 8; k++) {
            float4 a0 = *(const float4*)&As[k][ty * 4];
            float4 a1 = *(const float4*)&As[k][64 + ty * 4];
            float4 b0 = *(const float4*)&Bs[k][tx * 4];
            float4 b1 = *(const float4*)&Bs[k][64 + tx * 4];
            float a[8] = {a0.x, a0.y, a0.z, a0.w, a1.x, a1.y, a1.z, a1.w};
            float b[8] = {b0.x, b0.y, b0.z, b0.w, b1.x, b1.y, b1.z, b1.w};
#pragma unroll
            for (int i = 0; i < 8; i++)
#pragma unroll
                for (int j = 0; j < 8; j++)
                    acc[i][j] += a[i] * b[j];
        }
        __syncthreads();
    }
    const int rbase[2] = {bm + ty * 4, bm + 64 + ty * 4};
    const int cbase[2] = {bn + tx * 4, bn + 64 + tx * 4};
#pragma unroll
    for (int jh = 0; jh < 2; jh++) {
        const int col = cbase[jh];
        float4 bv = *(const float4*)&bias[col];
#pragma unroll
        for (int ih = 0; ih < 2; ih++) {
#pragma unroll
            for (int i = 0; i < 4; i++) {
                const int row = rbase[ih] + i;
                float4 v;
                v.x = acc[ih * 4 + i][jh * 4 + 0] + bv.x;
                v.y = acc[ih * 4 + i][jh * 4 + 1] + bv.y;
                v.z = acc[ih * 4 + i][jh * 4 + 2] + bv.z;
                v.w = acc[ih * 4 + i][jh * 4 + 3] + bv.w;
                v.x = v.x > 0.f ? v.x : 0.f;
                v.y = v.y > 0.f ? v.y : 0.f;
                v.z = v.z > 0.f ? v.z : 0.f;
                v.w = v.w > 0.f ? v.w : 0.f;
                __nv_bfloat162 p0 = __floats2bfloat162_rn(v.x, v.y);
                __nv_bfloat162 p1 = __floats2bfloat162_rn(v.z, v.w);
                uint2 pk; pk.x = *(uint32_t*)&p0; pk.y = *(uint32_t*)&p1;
                *(uint2*)&C[(size_t)row * N + col] = pk;
            }
        }
    }
}

// ===========================================================================
// Interaction: 3 samples/CTA; gram in fp32; bf16 output (padded to 512).
// ===========================================================================
__global__ __launch_bounds__(96)
void interact2(const __nv_bfloat16* __restrict__ bottom,
               const int* __restrict__ cat,
               const float* __restrict__ emb,
               __nv_bfloat16* __restrict__ x) {
    __shared__ float feats[3][NUM_FEATS][132];
    const int tid = threadIdx.x;
    const int b0 = blockIdx.x * 3;

    for (int idx = tid; idx < 3 * NUM_FEATS * 32; idx += 96) {
        const int s = idx / (NUM_FEATS * 32);
        const int rem = idx % (NUM_FEATS * 32);
        const int r = rem >> 5, q = rem & 31;
        const int b = b0 + s;
        if (b >= BATCH) continue;
        float4 v;
        if (r == 0) {
            uint2 raw = *(const uint2*)(bottom + (size_t)b * 128 + q * 4);
            __nv_bfloat162 p0 = *(__nv_bfloat162*)&raw.x;
            __nv_bfloat162 p1 = *(__nv_bfloat162*)&raw.y;
            v.x = __bfloat162float(p0.x); v.y = __bfloat162float(p0.y);
            v.z = __bfloat162float(p1.x); v.w = __bfloat162float(p1.y);
        } else {
            const int ci = cat[(size_t)(r - 1) * BATCH + b];
            v = *(const float4*)(emb + ((size_t)(r - 1) * TABLE_SIZE + ci) * 128 + q * 4);
        }
        feats[s][r][q * 4 + 0] = v.x;
        feats[s][r][q * 4 + 1] = v.y;
        feats[s][r][q * 4 + 2] = v.z;
        feats[s][r][q * 4 + 3] = v.w;
    }
    __syncthreads();

    {   // bottom copy (cols 0..127) + zero pad (cols 479..511)
        const int s = tid >> 5, q = tid & 31;
        const int b = b0 + s;
        if (b < BATCH) {
            __nv_bfloat16* xb = x + (size_t)b * TOP_IN_P;
            float4 v = *(const float4*)&feats[s][0][q * 4];
            __nv_bfloat162 p0 = __floats2bfloat162_rn(v.x, v.y);
            __nv_bfloat162 p1 = __floats2bfloat162_rn(v.z, v.w);
            uint2 pk; pk.x = *(uint32_t*)&p0; pk.y = *(uint32_t*)&p1;
            *(uint2*)(xb + q * 4) = pk;
            if (q == 0) {
                for (int c = TOP_IN - 1; c < TOP_IN_P; c++)
                    xb[c] = __float2bfloat16(0.f);
            }
        }
    }

    if (tid < 84) {
        const int s = tid / 28, blk = tid % 28;
        const int b = b0 + s;
        if (b < BATCH) {
            int R = 0;
            while ((R + 1) * (R + 2) / 2 <= blk) R++;
            const int Cc = blk - R * (R + 1) / 2;
            const int r0 = 4 * R, c0 = 4 * Cc;
            const float (*fs)[132] = feats[s];

            float acc[4][4];
#pragma unroll
            for (int i = 0; i < 4; i++)
#pragma unroll
                for (int j = 0; j < 4; j++) acc[i][j] = 0.f;

            const int ra[4] = {r0 < 27 ? r0 : 0, r0 + 1 < 27 ? r0 + 1 : 0,
                               r0 + 2 < 27 ? r0 + 2 : 0, r0 + 3 < 27 ? r0 + 3 : 0};
            const int ca[4] = {c0 < 27 ? c0 : 0, c0 + 1 < 27 ? c0 + 1 : 0,
                               c0 + 2 < 27 ? c0 + 2 : 0, c0 + 3 < 27 ? c0 + 3 : 0};

            for (int k = 0; k < 128; k += 4) {
                float4 av[4], bv[4];
#pragma unroll
                for (int i = 0; i < 4; i++) av[i] = *(const float4*)&fs[ra[i]][k];
#pragma unroll
                for (int j = 0; j < 4; j++) bv[j] = *(const float4*)&fs[ca[j]][k];
#pragma unroll
                for (int i = 0; i < 4; i++)
#pragma unroll
                    for (int j = 0; j < 4; j++)
                        acc[i][j] += av[i].x * bv[j].x + av[i].y * bv[j].y +
                                     av[i].z * bv[j].z + av[i].w * bv[j].w;
            }
            __nv_bfloat16* xb = x + (size_t)b * TOP_IN_P;
#pragma unroll
            for (int i = 0; i < 4; i++)
#pragma unroll
                for (int j = 0; j < 4; j++) {
                    const int r = r0 + i, c = c0 + j;
                    if (r < NUM_FEATS && c < r)
                        xb[128 + r * (r - 1) / 2 + c] = __float2bfloat16(acc[i][j]);
                }
        }
    }
}

// ===========================================================================
__global__ void round_bf16(const float* __restrict__ src,
                           __nv_bfloat16* __restrict__ dst, int n) {
    int i = blockIdx.x * blockDim.x + threadIdx.x;
    if (i < n) dst[i] = __float2bfloat16(src[i]);
}

// tw1 [1024 x 480] -> padded [1024 x 512] bf16 (zeros in K=480..511)
__global__ void round_bf16_pad(const float* __restrict__ src,
                               __nv_bfloat16* __restrict__ dst) {
    int i = blockIdx.x * blockDim.x + threadIdx.x;
    if (i < 1024 * TOP_IN_P) {
        int n = i / TOP_IN_P, k = i % TOP_IN_P;
        dst[i] = (k < TOP_IN) ? __float2bfloat16(src[n * TOP_IN + k])
                              : __float2bfloat16(0.f);
    }
}

// ===========================================================================
// Final layer: sigmoid(dot(t4_bf16, w5_fp32) + b5). Warp per sample.
// ===========================================================================
__global__ __launch_bounds__(256)
void final_layer(const __nv_bfloat16* __restrict__ A,
                 const float* __restrict__ w5,
                 const float* __restrict__ b5, float* __restrict__ out) {
    const int gwarp = (blockIdx.x * blockDim.x + threadIdx.x) >> 5;
    const int lane = threadIdx.x & 31;
    if (gwarp >= BATCH) return;
    // 256 bf16 = 32 x 16B chunks; one chunk (8 values) per lane
    uint4 raw = *(const uint4*)(A + (size_t)gwarp * 256 + lane * 8);
    const float4* w4 = (const float4*)(w5 + lane * 8);
    float4 w0 = w4[0], w1 = w4[1];
    __nv_bfloat162 p0 = *(__nv_bfloat162*)&raw.x;
    __nv_bfloat162 p1 = *(__nv_bfloat162*)&raw.y;
    __nv_bfloat162 p2 = *(__nv_bfloat162*)&raw.z;
    __nv_bfloat162 p3 = *(__nv_bfloat162*)&raw.w;
    float s = __bfloat162float(p0.x) * w0.x + __bfloat162float(p0.y) * w0.y +
              __bfloat162float(p1.x) * w0.z + __bfloat162float(p1.y) * w0.w +
              __bfloat162float(p2.x) * w1.x + __bfloat162float(p2.y) * w1.y +
              __bfloat162float(p3.x) * w1.z + __bfloat162float(p3.y) * w1.w;
#pragma unroll
    for (int o = 16; o; o >>= 1) s += __shfl_xor_sync(0xffffffffu, s, o);
    if (lane == 0) out[gwarp] = 1.f / (1.f + expf(-(s + b5[0])));
}

// ===========================================================================
extern "C" void kernel_launch(void* const* d_in, const int* in_sizes, int n_in,
                              void* d_out, int out_size) {
    const float* num = (const float*)d_in[0];
    const int*   cat = (const int*)  d_in[1];
    const float* emb = (const float*)d_in[2];
    const float* bw1 = (const float*)d_in[3];
    const float* bb1 = (const float*)d_in[4];
    const float* bw2 = (const float*)d_in[5];
    const float* bb2 = (const float*)d_in[6];
    const float* bw3 = (const float*)d_in[7];
    const float* bb3 = (const float*)d_in[8];
    const float* tw1 = (const float*)d_in[9];
    const float* tb1 = (const float*)d_in[10];
    const float* tw2 = (const float*)d_in[11];
    const float* tb2 = (const float*)d_in[12];
    const float* tw3 = (const float*)d_in[13];
    const float* tb3 = (const float*)d_in[14];
    const float* tw4 = (const float*)d_in[15];
    const float* tb4 = (const float*)d_in[16];
    const float* tw5 = (const float*)d_in[17];
    const float* tb5 = (const float*)d_in[18];
    float* out = (float*)d_out;

    __nv_bfloat16 *h1, *h2, *bot, *x, *t1, *t2, *t3, *t4;
    __nv_bfloat16 *bw2r, *bw3r, *tw1r, *tw2r, *tw3r, *tw4r;
    cudaGetSymbolAddress((void**)&h1,  g_h1);
    cudaGetSymbolAddress((void**)&h2,  g_h2);
    cudaGetSymbolAddress((void**)&bot, g_bot);
    cudaGetSymbolAddress((void**)&x,   g_x);
    cudaGetSymbolAddress((void**)&t1,  g_t1);
    cudaGetSymbolAddress((void**)&t2,  g_t2);
    cudaGetSymbolAddress((void**)&t3,  g_t3);
    cudaGetSymbolAddress((void**)&t4,  g_t4);
    cudaGetSymbolAddress((void**)&bw2r, g_bw2r);
    cudaGetSymbolAddress((void**)&bw3r, g_bw3r);
    cudaGetSymbolAddress((void**)&tw1r, g_tw1r);
    cudaGetSymbolAddress((void**)&tw2r, g_tw2r);
    cudaGetSymbolAddress((void**)&tw3r, g_tw3r);
    cudaGetSymbolAddress((void**)&tw4r, g_tw4r);

    const int SMEM = 2 * STAGE_BYTES;   // 73728
    cudaFuncSetAttribute(bf16_gemm, cudaFuncAttributeMaxDynamicSharedMemorySize, SMEM);

    // round weights to bf16 into scratch
    round_bf16<<<(256 * 512  + 255) / 256, 256>>>(bw2, bw2r, 256 * 512);
    round_bf16<<<(128 * 256  + 255) / 256, 256>>>(bw3, bw3r, 128 * 256);
    round_bf16_pad<<<(1024 * TOP_IN_P + 255) / 256, 256>>>(tw1, tw1r);
    round_bf16<<<(1024 * 1024 + 255) / 256, 256>>>(tw2, tw2r, 1024 * 1024);
    round_bf16<<<(512 * 1024 + 255) / 256, 256>>>(tw3, tw3r, 512 * 1024);
    round_bf16<<<(256 * 512  + 255) / 256, 256>>>(tw4, tw4r, 256 * 512);

    const int MB = BATCH / 128;  // 128

    // bottom MLP
    sgemm_l1<<<dim3(4, MB), 256>>>(num, bw1, bb1, h1, 512, 13);
    bf16_gemm<<<dim3(2, MB), 256, SMEM>>>(h1, bw2r, bb2, h2, 256, 512);
    bf16_gemm<<<dim3(1, MB), 256, SMEM>>>(h2, bw3r, bb3, bot, 128, 256);

    // embedding gather + interaction
    interact2<<<(BATCH + 2) / 3, 96>>>(bot, cat, emb, x);

    // top MLP (K padded to 512 for layer 1)
    bf16_gemm<<<dim3(8, MB), 256, SMEM>>>(x,  tw1r, tb1, t1, 1024, TOP_IN_P);
    bf16_gemm<<<dim3(8, MB), 256, SMEM>>>(t1, tw2r, tb2, t2, 1024, 1024);
    bf16_gemm<<<dim3(4, MB), 256, SMEM>>>(t2, tw3r, tb3, t3, 512, 1024);
    bf16_gemm<<<dim3(2, MB), 256, SMEM>>>(t3, tw4r, tb4, t4, 256, 512);

    // final dot + sigmoid
    final_layer<<<(BATCH * 32 + 255) / 256, 256>>>(t4, tw5, tb5, out);
}